// round 11
// baseline (speedup 1.0000x reference)
#include <cuda_runtime.h>
#include <cuda_bf16.h>
#include <math.h>
#include <stdint.h>

// Problem constants
#define TT 8192      // tokens = B*S
#define HD 1024      // hidden
#define FD 4096      // ffn
#define NE 8         // experts
#define NSLOT (TT*2) // token-expert pairs (top-2)

// GEMM tiling: block 128x128, BK=32, 256 threads (8 warps: 4M x 2N, warp 32x64)
#define BM 128
#define BN 128
#define BK 32
#define ROWA 144                  // A row: 64B hi | 64B lo | 16B pad
#define ROWBB 528                 // B row: 256B hi | 256B lo | 16B pad
#define ASMOFF 0
#define BSMOFF (128 * ROWA)       // 18432
#define SMEMB (128 * ROWA + 32 * ROWBB)   // 35328 B static

// -------------------- device global scratch (~290 MB total; 544 MB is fatal)
__device__ int   g_cnt[NE];
__device__ int   g_off[NE];
__device__ int   g_cur[NE];
__device__ int   g_topi[TT*2];
__device__ float g_topw[TT*2];
__device__ int   g_perm[NSLOT];
__device__ float g_gw[NSLOT];
__device__ __align__(256) __nv_bfloat16 g_xhi[(size_t)TT*HD];     // 16 MB
__device__ __align__(256) __nv_bfloat16 g_xlo[(size_t)TT*HD];     // 16 MB
__device__ __align__(256) __nv_bfloat16 g_h1hi[(size_t)NSLOT*FD]; // 128 MB
__device__ __align__(256) __nv_bfloat16 g_h1lo[(size_t)NSLOT*FD]; // 128 MB

// -------------------- helpers ----------------------------------------------
__device__ __forceinline__ uint32_t smem_u32(const void* p) {
    uint32_t a;
    asm("{ .reg .u64 t; cvta.to.shared.u64 t, %1; cvt.u32.u64 %0, t; }"
        : "=r"(a) : "l"(p));
    return a;
}
__device__ __forceinline__ void ldsm4(uint32_t a, uint32_t r[4]) {
    asm volatile("ldmatrix.sync.aligned.m8n8.x4.shared.b16 {%0,%1,%2,%3}, [%4];"
                 : "=r"(r[0]), "=r"(r[1]), "=r"(r[2]), "=r"(r[3]) : "r"(a));
}
__device__ __forceinline__ void ldsm4t(uint32_t a, uint32_t r[4]) {
    asm volatile("ldmatrix.sync.aligned.m8n8.x4.trans.shared.b16 {%0,%1,%2,%3}, [%4];"
                 : "=r"(r[0]), "=r"(r[1]), "=r"(r[2]), "=r"(r[3]) : "r"(a));
}
__device__ __forceinline__ void mma16816(float d[4], const uint32_t a[4],
                                         uint32_t b0, uint32_t b1) {
    asm volatile(
        "mma.sync.aligned.m16n8k16.row.col.f32.bf16.bf16.f32 "
        "{%0,%1,%2,%3}, {%4,%5,%6,%7}, {%8,%9}, {%0,%1,%2,%3};"
        : "+f"(d[0]), "+f"(d[1]), "+f"(d[2]), "+f"(d[3])
        : "r"(a[0]), "r"(a[1]), "r"(a[2]), "r"(a[3]), "r"(b0), "r"(b1));
}
__device__ __forceinline__ uint32_t pack_bf2(__nv_bfloat16 a, __nv_bfloat16 b) {
    return (uint32_t)__bfloat16_as_ushort(a) | ((uint32_t)__bfloat16_as_ushort(b) << 16);
}
// split pair of floats -> packed bf16x2 hi and lo
__device__ __forceinline__ void split2(float v0, float v1, uint32_t& h, uint32_t& l) {
    __nv_bfloat16 h0 = __float2bfloat16(v0);
    __nv_bfloat16 h1 = __float2bfloat16(v1);
    __nv_bfloat16 l0 = __float2bfloat16(v0 - __bfloat162float(h0));
    __nv_bfloat16 l1 = __float2bfloat16(v1 - __bfloat162float(h1));
    h = pack_bf2(h0, h1);
    l = pack_bf2(l0, l1);
}

// ---------------------------------------------------------------------------
// Zero output + expert counters
// ---------------------------------------------------------------------------
__global__ void zero_kernel(float4* __restrict__ out4) {
    unsigned i = blockIdx.x * blockDim.x + threadIdx.x;
    const float4 z = make_float4(0.f, 0.f, 0.f, 0.f);
    out4[i] = z;
    out4[i + (TT * HD / 8)] = z;
    if (i < NE) g_cnt[i] = 0;
}

// ---------------------------------------------------------------------------
// Router: one warp per token (proven)
// ---------------------------------------------------------------------------
__global__ void router_kernel(const float* __restrict__ x,
                              const float* __restrict__ rw,
                              const float* __restrict__ rb) {
    int t    = (blockIdx.x * blockDim.x + threadIdx.x) >> 5;
    int lane = threadIdx.x & 31;
    if (t >= TT) return;

    const float* xp = x + (size_t)t * HD;
    float acc[NE];
#pragma unroll
    for (int e = 0; e < NE; e++) acc[e] = 0.f;

    for (int h = lane; h < HD; h += 32) {
        float xv = xp[h];
        const float4* r = (const float4*)(rw + (size_t)h * NE);
        float4 a = r[0], b = r[1];
        acc[0] += xv * a.x; acc[1] += xv * a.y; acc[2] += xv * a.z; acc[3] += xv * a.w;
        acc[4] += xv * b.x; acc[5] += xv * b.y; acc[6] += xv * b.z; acc[7] += xv * b.w;
    }
#pragma unroll
    for (int e = 0; e < NE; e++)
#pragma unroll
        for (int o = 16; o > 0; o >>= 1)
            acc[e] += __shfl_xor_sync(0xffffffffu, acc[e], o);

    if (lane == 0) {
        float l[NE];
#pragma unroll
        for (int e = 0; e < NE; e++) l[e] = acc[e] + rb[e];
        int i1 = 0;
#pragma unroll
        for (int e = 1; e < NE; e++) if (l[e] > l[i1]) i1 = e;
        int i2 = (i1 == 0) ? 1 : 0;
#pragma unroll
        for (int e = 0; e < NE; e++) if (e != i1 && l[e] > l[i2]) i2 = e;

        float d  = expf(l[i2] - l[i1]);
        float w1 = 1.f / (1.f + d);
        float w2 = d * w1;
        g_topi[2 * t + 0] = i1; g_topw[2 * t + 0] = w1;
        g_topi[2 * t + 1] = i2; g_topw[2 * t + 1] = w2;
        atomicAdd(&g_cnt[i1], 1);
        atomicAdd(&g_cnt[i2], 1);
    }
}

__global__ void prefix_kernel() {
    if (threadIdx.x == 0) {
        int s = 0;
        for (int e = 0; e < NE; e++) { g_off[e] = s; g_cur[e] = s; s += g_cnt[e]; }
    }
}

__global__ void scatter_kernel() {
    int t = blockIdx.x * blockDim.x + threadIdx.x;
    if (t >= TT) return;
#pragma unroll
    for (int k = 0; k < 2; k++) {
        int e = g_topi[2 * t + k];
        int p = atomicAdd(&g_cur[e], 1);
        g_perm[p] = t;
        g_gw[p]   = g_topw[2 * t + k];
    }
}

// ---------------------------------------------------------------------------
// x -> bf16 hi/lo split (elementwise, once per token instead of 32x in GEMM1)
// ---------------------------------------------------------------------------
__global__ void convert_x_kernel(const float4* __restrict__ x4) {
    size_t i = (size_t)blockIdx.x * blockDim.x + threadIdx.x;   // over TT*HD/4
    float4 v = x4[i];
    uint32_t h0, l0, h1, l1;
    split2(v.x, v.y, h0, l0);
    split2(v.z, v.w, h1, l1);
    ((uint2*)g_xhi)[i] = make_uint2(h0, h1);
    ((uint2*)g_xlo)[i] = make_uint2(l0, l1);
}

// ---------------------------------------------------------------------------
// Grouped HMMA GEMM, 3-pass split-bf16 (hi*hi + hi*lo + lo*hi), fp32 acc.
// A operand is PRE-SPLIT bf16 (x or h1): staging = pure 64B copies.
// B operand (weights, [E][K][N] fp32) split in-kernel during staging.
// MODE 0: h1[slot] = gelu(gather(x) @ w1[e] + b1[e])   -> bf16 hi/lo
// MODE 1: out[tok] += gw * (h1[slot] @ w2[e] + b2[e])  (atomic combine)
// ---------------------------------------------------------------------------
template <int MODE>
__global__ void __launch_bounds__(256, 2) moe_mma_kernel(
    const float* __restrict__ wsrc,   // w1 / w2, layout [E][K][N]
    const float* __restrict__ bias,
    float* __restrict__ out)
{
    constexpr int KD     = (MODE == 0) ? HD : FD;
    constexpr int ND     = (MODE == 0) ? FD : HD;
    constexpr int NCHUNK = KD / BK;

    __shared__ __align__(16) char smem[SMEMB];
    const uint32_t sb = smem_u32(smem);

    const int e       = blockIdx.z;
    const int seg_len = g_cnt[e];
    const int m0      = blockIdx.x * BM;
    if (m0 >= seg_len) return;
    const int seg_off = g_off[e];
    const int n0      = blockIdx.y * BN;
    const int tid     = threadIdx.x;

    // ---- staging assignment ----
    // A: thread -> (row 0..127, half hi/lo), 64B (32 bf16) per chunk
    const int arow = tid >> 1, asel = tid & 1;
    const __nv_bfloat16* aptr;
    {
        int gr = m0 + arow;
        int cg = (gr < seg_len) ? gr : (seg_len - 1);
        if (MODE == 0) {
            int tok = g_perm[seg_off + cg];
            aptr = (asel ? g_xlo : g_xhi) + (size_t)tok * HD;
        } else {
            size_t s = (size_t)(seg_off + cg);
            aptr = (asel ? g_h1lo : g_h1hi) + s * FD;
        }
    }
    // B: thread -> (k-row 0..31, n-seg of 16), 16 fp32 each
    const int brow = tid >> 3, bseg = (tid & 7) * 16;
    const float* bptr = wsrc + (size_t)e * KD * ND + (size_t)brow * ND + n0 + bseg;

    uint4* aD   = (uint4*)(smem + ASMOFF + arow * ROWA + asel * 64);
    uint4* bHiD = (uint4*)(smem + BSMOFF + brow * ROWBB + bseg * 2);
    uint4* bLoD = (uint4*)(smem + BSMOFF + brow * ROWBB + 256 + bseg * 2);

    // ---- fragment addressing ----
    const int wid = tid >> 5, lane = tid & 31;
    const int wM = wid & 3, wN = wid >> 2;   // 4 x 2 warp grid, warp tile 32x64
    const uint32_t aF = sb + (uint32_t)((wM * 32 + (lane & 15)) * ROWA
                                        + (lane >> 4) * 16);
    const int bkrow = (lane & 7) + ((lane >> 3) & 1) * 8;
    const int bnoff = (lane >> 4) * 8;
    const uint32_t bF = sb + (uint32_t)BSMOFF
                      + (uint32_t)(bkrow * ROWBB + (wN * 64 + bnoff) * 2);

    float acc[2][8][4];
#pragma unroll
    for (int mf = 0; mf < 2; mf++)
#pragma unroll
        for (int nf = 0; nf < 8; nf++)
#pragma unroll
            for (int r = 0; r < 4; r++) acc[mf][nf][r] = 0.f;

    uint4  pa[4];
    float4 pb[4];
    auto ldA = [&](int kt) {
        const uint4* p = (const uint4*)(aptr + kt);      // 32 bf16 = 4 x uint4
#pragma unroll
        for (int i = 0; i < 4; i++) pa[i] = p[i];
    };
    auto ldB = [&](int kt) {
        const float4* p = (const float4*)(bptr + (size_t)kt * ND);
#pragma unroll
        for (int i = 0; i < 4; i++) pb[i] = p[i];
    };
    auto stStage = [&]() {
#pragma unroll
        for (int i = 0; i < 4; i++) aD[i] = pa[i];       // pure copy
        uint32_t h[8], l[8];
#pragma unroll
        for (int i = 0; i < 4; i++) {
            split2(pb[i].x, pb[i].y, h[2 * i], l[2 * i]);
            split2(pb[i].z, pb[i].w, h[2 * i + 1], l[2 * i + 1]);
        }
        bHiD[0] = make_uint4(h[0], h[1], h[2], h[3]);
        bHiD[1] = make_uint4(h[4], h[5], h[6], h[7]);
        bLoD[0] = make_uint4(l[0], l[1], l[2], l[3]);
        bLoD[1] = make_uint4(l[4], l[5], l[6], l[7]);
    };

    ldA(0); ldB(0);

#pragma unroll 1
    for (int c = 0; c < NCHUNK; c++) {
        __syncthreads();            // previous chunk's MMAs done; smem free
        stStage();
        __syncthreads();
        if (c + 1 < NCHUNK) { ldA((c + 1) * BK); ldB((c + 1) * BK); }

#pragma unroll
        for (int k16 = 0; k16 < 2; k16++) {
            uint32_t ah[2][4], al[2][4];
            const uint32_t ka = aF + (uint32_t)(k16 * 32);
            ldsm4(ka,                  ah[0]);
            ldsm4(ka + 16 * ROWA,      ah[1]);
            ldsm4(ka + 64,             al[0]);
            ldsm4(ka + 64 + 16 * ROWA, al[1]);
            const uint32_t kb = bF + (uint32_t)(k16 * 16 * ROWBB);
#pragma unroll
            for (int g2 = 0; g2 < 4; g2++) {
                uint32_t bh[4], bl[4];
                ldsm4t(kb + g2 * 32,       bh);
                ldsm4t(kb + 256 + g2 * 32, bl);
#pragma unroll
                for (int mf = 0; mf < 2; mf++) {
                    mma16816(acc[mf][2 * g2 + 0], ah[mf], bh[0], bh[1]);
                    mma16816(acc[mf][2 * g2 + 1], ah[mf], bh[2], bh[3]);
                    mma16816(acc[mf][2 * g2 + 0], ah[mf], bl[0], bl[1]);
                    mma16816(acc[mf][2 * g2 + 1], ah[mf], bl[2], bl[3]);
                    mma16816(acc[mf][2 * g2 + 0], al[mf], bh[0], bh[1]);
                    mma16816(acc[mf][2 * g2 + 1], al[mf], bh[2], bh[3]);
                }
            }
        }
    }

    // ---- epilogue ----
    // D frag: thread holds rows (lane>>2), (lane>>2)+8; cols (lane&3)*2, +1
    const float* bp = bias + (size_t)e * ND + n0 + wN * 64 + (lane & 3) * 2;
    float bv[16];
#pragma unroll
    for (int nf = 0; nf < 8; nf++) {
        bv[2 * nf + 0] = __ldg(bp + nf * 8);
        bv[2 * nf + 1] = __ldg(bp + nf * 8 + 1);
    }
    const int colBase = n0 + wN * 64 + (lane & 3) * 2;

#pragma unroll
    for (int mf = 0; mf < 2; mf++) {
#pragma unroll
        for (int half = 0; half < 2; half++) {
            int gr = m0 + wM * 32 + mf * 16 + (lane >> 2) + half * 8;
            if (gr >= seg_len) continue;
            int slot = seg_off + gr;
            if (MODE == 0) {
                __nv_bfloat16* oh = g_h1hi + (size_t)slot * FD;
                __nv_bfloat16* ol = g_h1lo + (size_t)slot * FD;
#pragma unroll
                for (int nf = 0; nf < 8; nf++) {
                    float v0 = acc[mf][nf][2 * half + 0] + bv[2 * nf + 0];
                    float v1 = acc[mf][nf][2 * half + 1] + bv[2 * nf + 1];
                    float c0 = v0 + 0.044715f * v0 * v0 * v0;
                    float c1 = v1 + 0.044715f * v1 * v1 * v1;
                    float g0 = 0.5f * v0 * (1.f + tanhf(0.7978845608028654f * c0));
                    float g1 = 0.5f * v1 * (1.f + tanhf(0.7978845608028654f * c1));
                    uint32_t hh, ll;
                    split2(g0, g1, hh, ll);
                    int col = colBase + nf * 8;
                    *(uint32_t*)(oh + col) = hh;
                    *(uint32_t*)(ol + col) = ll;
                }
            } else {
                int   tok = g_perm[slot];
                float w   = g_gw[slot];
                float* op = out + (size_t)tok * HD;
#pragma unroll
                for (int nf = 0; nf < 8; nf++) {
                    int col = colBase + nf * 8;
                    atomicAdd(op + col,
                              w * (acc[mf][nf][2 * half + 0] + bv[2 * nf + 0]));
                    atomicAdd(op + col + 1,
                              w * (acc[mf][nf][2 * half + 1] + bv[2 * nf + 1]));
                }
            }
        }
    }
}

// ---------------------------------------------------------------------------
// Launch
// ---------------------------------------------------------------------------
extern "C" void kernel_launch(void* const* d_in, const int* in_sizes, int n_in,
                              void* d_out, int out_size) {
    const float* x  = (const float*)d_in[0];   // [B,S,H]
    const float* w1 = (const float*)d_in[1];   // [E,H,F]  = [E][K][N] for GEMM1
    const float* b1 = (const float*)d_in[2];   // [E,F]
    const float* w2 = (const float*)d_in[3];   // [E,F,H]  = [E][K][N] for GEMM2
    const float* b2 = (const float*)d_in[4];   // [E,H]
    const float* rw = (const float*)d_in[5];   // [H,E]
    const float* rb = (const float*)d_in[6];   // [E]
    float* out = (float*)d_out;

    zero_kernel<<<4096, 256>>>((float4*)out);
    router_kernel<<<TT / 8, 256>>>(x, rw, rb);
    prefix_kernel<<<1, 32>>>();
    scatter_kernel<<<TT / 256, 256>>>();
    convert_x_kernel<<<(TT * HD / 4) / 256, 256>>>((const float4*)x);

    // GEMM1: gelu(gather(x) @ w1 + b1) -> h1 (bf16 hi/lo)
    moe_mma_kernel<0><<<dim3(128, FD / BN, NE), 256>>>(w1, b1, nullptr);
    // GEMM2: h1 @ w2 + b2, weighted atomic combine into out
    moe_mma_kernel<1><<<dim3(128, HD / BN, NE), 256>>>(w2, b2, out);
}